// round 1
// baseline (speedup 1.0000x reference)
#include <cuda_runtime.h>
#include <cuda_bf16.h>

#define MAX_N 100000
#define FULLMASK 0xffffffffu

// Scratch intermediates (no allocation allowed): [N,64] each, ~25.6MB each.
__device__ float g_mid1[MAX_N * 64];
__device__ float g_mid2[MAX_N * 64];

// ---------------------------------------------------------------------------
// conv1: mid1 = relu((features @ w1) * scale1 + bias1)    [N,256]x[256,64]
// Warp processes 4 rows; lane owns output cols {lane, lane+32}.
// w1 staged in smem as float2 pairs (col lane / col lane+32), 64KB.
// ---------------------------------------------------------------------------
__global__ void __launch_bounds__(256) conv1_kernel(
    const float* __restrict__ feat,
    const float* __restrict__ w1,
    const float* __restrict__ scale1,
    const float* __restrict__ bias1,
    int N)
{
    extern __shared__ float2 w1p[];  // [256][32] float2 = 64KB
    for (int i = threadIdx.x; i < 256 * 32; i += blockDim.x) {
        int k = i >> 5, l = i & 31;
        w1p[i] = make_float2(w1[k * 64 + l], w1[k * 64 + l + 32]);
    }
    __syncthreads();

    const int lane = threadIdx.x & 31;
    const int gw = (blockIdx.x * blockDim.x + threadIdx.x) >> 5;
    const int nw = (gridDim.x * blockDim.x) >> 5;

    const float s0 = scale1[lane], s1 = scale1[lane + 32];
    const float b0 = bias1[lane],  b1 = bias1[lane + 32];

    for (int base = gw * 4; base < N; base += nw * 4) {
        float acc0[4] = {0.f, 0.f, 0.f, 0.f};
        float acc1[4] = {0.f, 0.f, 0.f, 0.f};

        for (int k0 = 0; k0 < 256; k0 += 32) {
            float xv[4];
            #pragma unroll
            for (int i = 0; i < 4; i++) {
                int row = base + i;
                xv[i] = (row < N) ? feat[(size_t)row * 256 + k0 + lane] : 0.f;
            }
            #pragma unroll
            for (int j = 0; j < 32; j++) {
                float2 w = w1p[(k0 + j) * 32 + lane];
                #pragma unroll
                for (int i = 0; i < 4; i++) {
                    float x = __shfl_sync(FULLMASK, xv[i], j);
                    acc0[i] = fmaf(x, w.x, acc0[i]);
                    acc1[i] = fmaf(x, w.y, acc1[i]);
                }
            }
        }
        #pragma unroll
        for (int i = 0; i < 4; i++) {
            int row = base + i;
            if (row < N) {
                g_mid1[(size_t)row * 64 + lane]      = fmaxf(fmaf(acc0[i], s0, b0), 0.f);
                g_mid1[(size_t)row * 64 + lane + 32] = fmaxf(fmaf(acc1[i], s1, b1), 0.f);
            }
        }
    }
}

// ---------------------------------------------------------------------------
// conv2: mid2 = relu((sum_k gather(mid1, nbr[:,k]) @ w2[k]) * scale2 + bias2)
// Warp processes 4 rows; lane owns cols {lane, lane+32}.
// w2 staged in smem as float2 pairs, 9*64*32 float2 = 144KB.
// Sentinel nbr index == N -> zero contribution (matches zero-padded gather).
// ---------------------------------------------------------------------------
__global__ void __launch_bounds__(512) conv2_kernel(
    const int* __restrict__ nbr,
    const float* __restrict__ w2,
    const float* __restrict__ scale2,
    const float* __restrict__ bias2,
    int N)
{
    extern __shared__ float2 w2p[];  // [9][64][32] float2 = 147456B
    for (int i = threadIdx.x; i < 9 * 64 * 32; i += blockDim.x) {
        int k = i / 2048;
        int r = i & 2047;
        int c = r >> 5, l = r & 31;
        w2p[i] = make_float2(w2[k * 4096 + c * 64 + l],
                             w2[k * 4096 + c * 64 + l + 32]);
    }
    __syncthreads();

    const int lane = threadIdx.x & 31;
    const int gw = (blockIdx.x * blockDim.x + threadIdx.x) >> 5;
    const int nw = (gridDim.x * blockDim.x) >> 5;

    const float s0 = scale2[lane], s1 = scale2[lane + 32];
    const float b0 = bias2[lane],  b1 = bias2[lane + 32];

    for (int base = gw * 4; base < N; base += nw * 4) {
        float acc0[4] = {0.f, 0.f, 0.f, 0.f};
        float acc1[4] = {0.f, 0.f, 0.f, 0.f};

        for (int k = 0; k < 9; k++) {
            float ga[4], gb[4];
            #pragma unroll
            for (int i = 0; i < 4; i++) {
                int row = base + i;
                int nidx = (row < N) ? nbr[row * 9 + k] : N;
                if (nidx < N) {
                    ga[i] = g_mid1[(size_t)nidx * 64 + lane];
                    gb[i] = g_mid1[(size_t)nidx * 64 + lane + 32];
                } else {
                    ga[i] = 0.f; gb[i] = 0.f;
                }
            }
            const float2* wk = w2p + k * 2048;
            #pragma unroll
            for (int j = 0; j < 32; j++) {
                float2 wa = wk[j * 32 + lane];          // c = j
                float2 wb = wk[(j + 32) * 32 + lane];   // c = j + 32
                #pragma unroll
                for (int i = 0; i < 4; i++) {
                    float x0 = __shfl_sync(FULLMASK, ga[i], j);
                    float x1 = __shfl_sync(FULLMASK, gb[i], j);
                    acc0[i] = fmaf(x0, wa.x, fmaf(x1, wb.x, acc0[i]));
                    acc1[i] = fmaf(x0, wa.y, fmaf(x1, wb.y, acc1[i]));
                }
            }
        }
        #pragma unroll
        for (int i = 0; i < 4; i++) {
            int row = base + i;
            if (row < N) {
                g_mid2[(size_t)row * 64 + lane]      = fmaxf(fmaf(acc0[i], s0, b0), 0.f);
                g_mid2[(size_t)row * 64 + lane + 32] = fmaxf(fmaf(acc1[i], s1, b1), 0.f);
            }
        }
    }
}

// ---------------------------------------------------------------------------
// conv3: out = relu((mid2 @ w3) * scale3 + bias3 + features)  [N,64]x[64,256]
// Warp processes 4 rows; lane owns cols {4*lane..4*lane+3} and {128+4*lane..}.
// w3 staged in smem as float4, 64KB. Fully vectorized loads/stores.
// ---------------------------------------------------------------------------
__global__ void __launch_bounds__(256) conv3_kernel(
    const float* __restrict__ feat,
    const float* __restrict__ w3,
    const float* __restrict__ scale3,
    const float* __restrict__ bias3,
    float* __restrict__ out,
    int N)
{
    extern __shared__ float4 w3s[];  // [64][64] float4 = 64KB  (w3 as [64][256] f32)
    {
        const float4* w3v = (const float4*)w3;
        for (int i = threadIdx.x; i < 64 * 64; i += blockDim.x) w3s[i] = w3v[i];
    }
    __syncthreads();

    const int lane = threadIdx.x & 31;
    const int gw = (blockIdx.x * blockDim.x + threadIdx.x) >> 5;
    const int nw = (gridDim.x * blockDim.x) >> 5;

    const float4* s3v = (const float4*)scale3;
    const float4* b3v = (const float4*)bias3;
    const float4 sA = s3v[lane], sB = s3v[32 + lane];
    const float4 bA = b3v[lane], bB = b3v[32 + lane];

    const float4* featv = (const float4*)feat;
    float4* outv = (float4*)out;

    for (int base = gw * 4; base < N; base += nw * 4) {
        float4 A[4], B[4];
        #pragma unroll
        for (int i = 0; i < 4; i++) {
            A[i] = make_float4(0.f, 0.f, 0.f, 0.f);
            B[i] = make_float4(0.f, 0.f, 0.f, 0.f);
        }
        float m0[4], m1[4];
        #pragma unroll
        for (int i = 0; i < 4; i++) {
            int row = base + i;
            m0[i] = (row < N) ? g_mid2[(size_t)row * 64 + lane]      : 0.f;
            m1[i] = (row < N) ? g_mid2[(size_t)row * 64 + lane + 32] : 0.f;
        }

        #pragma unroll 8
        for (int j = 0; j < 32; j++) {
            float4 wa = w3s[j * 64 + lane];             // k = j,    cols 4*lane..
            float4 wb = w3s[j * 64 + 32 + lane];        // k = j,    cols 128+4*lane..
            float4 wc = w3s[(j + 32) * 64 + lane];      // k = j+32
            float4 wd = w3s[(j + 32) * 64 + 32 + lane];
            #pragma unroll
            for (int i = 0; i < 4; i++) {
                float x0 = __shfl_sync(FULLMASK, m0[i], j);
                float x1 = __shfl_sync(FULLMASK, m1[i], j);
                A[i].x = fmaf(x0, wa.x, fmaf(x1, wc.x, A[i].x));
                A[i].y = fmaf(x0, wa.y, fmaf(x1, wc.y, A[i].y));
                A[i].z = fmaf(x0, wa.z, fmaf(x1, wc.z, A[i].z));
                A[i].w = fmaf(x0, wa.w, fmaf(x1, wc.w, A[i].w));
                B[i].x = fmaf(x0, wb.x, fmaf(x1, wd.x, B[i].x));
                B[i].y = fmaf(x0, wb.y, fmaf(x1, wd.y, B[i].y));
                B[i].z = fmaf(x0, wb.z, fmaf(x1, wd.z, B[i].z));
                B[i].w = fmaf(x0, wb.w, fmaf(x1, wd.w, B[i].w));
            }
        }

        #pragma unroll
        for (int i = 0; i < 4; i++) {
            int row = base + i;
            if (row < N) {
                float4 r0 = featv[(size_t)row * 64 + lane];
                float4 r1 = featv[(size_t)row * 64 + 32 + lane];
                float4 o0, o1;
                o0.x = fmaxf(fmaf(A[i].x, sA.x, bA.x) + r0.x, 0.f);
                o0.y = fmaxf(fmaf(A[i].y, sA.y, bA.y) + r0.y, 0.f);
                o0.z = fmaxf(fmaf(A[i].z, sA.z, bA.z) + r0.z, 0.f);
                o0.w = fmaxf(fmaf(A[i].w, sA.w, bA.w) + r0.w, 0.f);
                o1.x = fmaxf(fmaf(B[i].x, sB.x, bB.x) + r1.x, 0.f);
                o1.y = fmaxf(fmaf(B[i].y, sB.y, bB.y) + r1.y, 0.f);
                o1.z = fmaxf(fmaf(B[i].z, sB.z, bB.z) + r1.z, 0.f);
                o1.w = fmaxf(fmaf(B[i].w, sB.w, bB.w) + r1.w, 0.f);
                outv[(size_t)row * 64 + lane]      = o0;
                outv[(size_t)row * 64 + 32 + lane] = o1;
            }
        }
    }
}

// ---------------------------------------------------------------------------
extern "C" void kernel_launch(void* const* d_in, const int* in_sizes, int n_in,
                              void* d_out, int out_size)
{
    const float* feat = (const float*)d_in[0];
    const int*   nbr  = (const int*)  d_in[1];
    const float* w1   = (const float*)d_in[2];
    const float* s1   = (const float*)d_in[3];
    const float* b1   = (const float*)d_in[4];
    const float* w2   = (const float*)d_in[5];
    const float* s2   = (const float*)d_in[6];
    const float* b2   = (const float*)d_in[7];
    const float* w3   = (const float*)d_in[8];
    const float* s3   = (const float*)d_in[9];
    const float* b3   = (const float*)d_in[10];
    float* out = (float*)d_out;

    int N = in_sizes[0] / 256;
    if (N > MAX_N) N = MAX_N;

    const size_t sm1 = 256 * 32 * sizeof(float2);   // 65536
    const size_t sm2 = 9 * 64 * 32 * sizeof(float2); // 147456
    const size_t sm3 = 64 * 64 * sizeof(float4);    // 65536

    cudaFuncSetAttribute(conv1_kernel, cudaFuncAttributeMaxDynamicSharedMemorySize, (int)sm1);
    cudaFuncSetAttribute(conv2_kernel, cudaFuncAttributeMaxDynamicSharedMemorySize, (int)sm2);
    cudaFuncSetAttribute(conv3_kernel, cudaFuncAttributeMaxDynamicSharedMemorySize, (int)sm3);

    conv1_kernel<<<456, 256, sm1>>>(feat, w1, s1, b1, N);
    conv2_kernel<<<304, 512, sm2>>>(nbr, w2, s2, b2, N);
    conv3_kernel<<<456, 256, sm3>>>(feat, w3, s3, b3, out, N);
}

// round 3
// speedup vs baseline: 1.9079x; 1.9079x over previous
#include <cuda_runtime.h>
#include <cuda_bf16.h>
#include <cstdint>

#define MAX_N 100000

// Packed bf16 hi/lo intermediates: u32 = hi | (lo<<16)
__device__ __align__(16) uint32_t g_mid1p[MAX_N * 64];
__device__ __align__(16) uint32_t g_mid2p[MAX_N * 64];
// Pre-split weights (transposed to [n][k])
__device__ __align__(16) uint32_t g_w1p[64 * 256];       // w1^T
__device__ __align__(16) uint32_t g_w2p[9 * 64 * 64];    // w2^T per offset
__device__ __align__(16) uint32_t g_w3p[256 * 64];       // w3^T

// ---------------- helpers ----------------
__device__ __forceinline__ uint32_t prmt(uint32_t a, uint32_t b, uint32_t s) {
    uint32_t d; asm("prmt.b32 %0,%1,%2,%3;" : "=r"(d) : "r"(a), "r"(b), "r"(s)); return d;
}
__device__ __forceinline__ uint32_t packf(float x) {
    __nv_bfloat16 h = __float2bfloat16(x);
    __nv_bfloat16 l = __float2bfloat16(x - __bfloat162float(h));
    return (uint32_t)__bfloat16_as_ushort(h) | ((uint32_t)__bfloat16_as_ushort(l) << 16);
}
__device__ __forceinline__ uint4 pack4(float4 v) {
    uint4 o; o.x = packf(v.x); o.y = packf(v.y); o.z = packf(v.z); o.w = packf(v.w); return o;
}
__device__ __forceinline__ void mma_bf16(float* c, uint32_t a0, uint32_t a1, uint32_t a2,
                                         uint32_t a3, uint32_t b0, uint32_t b1) {
    asm volatile(
        "mma.sync.aligned.m16n8k16.row.col.f32.bf16.bf16.f32 "
        "{%0,%1,%2,%3}, {%4,%5,%6,%7}, {%8,%9}, {%0,%1,%2,%3};"
        : "+f"(c[0]), "+f"(c[1]), "+f"(c[2]), "+f"(c[3])
        : "r"(a0), "r"(a1), "r"(a2), "r"(a3), "r"(b0), "r"(b1));
}

struct AFrag { uint32_t hi[4], lo[4]; };
struct BFrag { uint32_t hi[2], lo[2]; };

__device__ __forceinline__ AFrag load_a(const uint32_t* A, int S, int row0, int k0, int g, int tg) {
    const uint32_t* p = A + (row0 + g) * S + k0 + 2 * tg;
    uint2 q0 = *(const uint2*)p;
    uint2 q1 = *(const uint2*)(p + 8 * S);
    uint2 q2 = *(const uint2*)(p + 8);
    uint2 q3 = *(const uint2*)(p + 8 * S + 8);
    AFrag f;
    f.hi[0] = prmt(q0.x, q0.y, 0x5410); f.lo[0] = prmt(q0.x, q0.y, 0x7632);
    f.hi[1] = prmt(q1.x, q1.y, 0x5410); f.lo[1] = prmt(q1.x, q1.y, 0x7632);
    f.hi[2] = prmt(q2.x, q2.y, 0x5410); f.lo[2] = prmt(q2.x, q2.y, 0x7632);
    f.hi[3] = prmt(q3.x, q3.y, 0x5410); f.lo[3] = prmt(q3.x, q3.y, 0x7632);
    return f;
}
__device__ __forceinline__ BFrag load_b(const uint32_t* B, int S, int n0, int k0, int g, int tg) {
    const uint32_t* p = B + (n0 + g) * S + k0 + 2 * tg;
    uint2 r0 = *(const uint2*)p;
    uint2 r1 = *(const uint2*)(p + 8);
    BFrag f;
    f.hi[0] = prmt(r0.x, r0.y, 0x5410); f.lo[0] = prmt(r0.x, r0.y, 0x7632);
    f.hi[1] = prmt(r1.x, r1.y, 0x5410); f.lo[1] = prmt(r1.x, r1.y, 0x7632);
    return f;
}
__device__ __forceinline__ void mma3(float* c, const AFrag& a, const BFrag& b) {
    mma_bf16(c, a.hi[0], a.hi[1], a.hi[2], a.hi[3], b.hi[0], b.hi[1]);
    mma_bf16(c, a.hi[0], a.hi[1], a.hi[2], a.hi[3], b.lo[0], b.lo[1]);
    mma_bf16(c, a.lo[0], a.lo[1], a.lo[2], a.lo[3], b.hi[0], b.hi[1]);
}

// ---------------- prep: split weights to bf16 hi/lo, transpose to [n][k] ----
__global__ void prep_weights(const float* __restrict__ w1, const float* __restrict__ w2,
                             const float* __restrict__ w3) {
    int tid = blockIdx.x * blockDim.x + threadIdx.x;
    int nt = gridDim.x * blockDim.x;
    for (int i = tid; i < 64 * 256; i += nt) {            // g_w1p[n*256+k]
        int n = i >> 8, k = i & 255;
        g_w1p[i] = packf(w1[k * 64 + n]);
    }
    for (int i = tid; i < 9 * 64 * 64; i += nt) {         // g_w2p[ko*4096+n*64+k]
        int ko = i >> 12, r = i & 4095, n = r >> 6, k = r & 63;
        g_w2p[i] = packf(w2[ko * 4096 + k * 64 + n]);
    }
    for (int i = tid; i < 256 * 64; i += nt) {            // g_w3p[n*64+k]
        int n = i >> 6, k = i & 63;
        g_w3p[i] = packf(w3[k * 256 + n]);
    }
}

// ===========================================================================
// conv1: mid1p = split(relu((feat @ w1)*s1+b1))   M128 tile, K=256, N=64
// smem: A[128][264] u32 (135KB) + B[64][264] u32 (67.6KB) = 202,752 B
// 512 thr, 16 warps, warp-tile M32xN16
// ===========================================================================
__global__ void __launch_bounds__(512) conv1_k(
    const float* __restrict__ feat, const float* __restrict__ scale,
    const float* __restrict__ bias, int N, int tiles)
{
    extern __shared__ uint32_t sm[];
    uint32_t* Asm = sm;                 // stride 264
    uint32_t* Bsm = sm + 128 * 264;     // stride 264
    const int tid = threadIdx.x, w = tid >> 5, lane = tid & 31;
    const int g = lane >> 2, tg = lane & 3;
    const int m0w = (w & 3) * 32, n0w = (w >> 2) * 16;
    const int sr = tid >> 2, sq = tid & 3;

    for (int e = tid; e < 4096; e += 512) {   // B: 64 rows x 64 uint4
        uint4 v = ((const uint4*)g_w1p)[e];
        int n = e >> 6, kq = e & 63;
        *(uint4*)(Bsm + n * 264 + kq * 4) = v;
    }
    __syncthreads();

    for (int t = blockIdx.x; t < tiles; t += gridDim.x) {
        const int row0 = t << 7;
        const int grow = row0 + sr;
        #pragma unroll 4
        for (int j = 0; j < 16; j++) {
            int k4 = sq * 64 + j * 4;
            float4 v = (grow < N) ? *(const float4*)(feat + (size_t)grow * 256 + k4)
                                  : make_float4(0.f, 0.f, 0.f, 0.f);
            *(uint4*)(Asm + sr * 264 + k4) = pack4(v);
        }
        __syncthreads();

        float C[2][2][4] = {};
        #pragma unroll 2
        for (int s = 0; s < 16; s++) {
            int k0 = s * 16;
            AFrag a0 = load_a(Asm, 264, m0w, k0, g, tg);
            AFrag a1 = load_a(Asm, 264, m0w + 16, k0, g, tg);
            BFrag b0 = load_b(Bsm, 264, n0w, k0, g, tg);
            BFrag b1 = load_b(Bsm, 264, n0w + 8, k0, g, tg);
            mma3(C[0][0], a0, b0); mma3(C[0][1], a0, b1);
            mma3(C[1][0], a1, b0); mma3(C[1][1], a1, b1);
        }
        #pragma unroll
        for (int mf = 0; mf < 2; mf++)
        #pragma unroll
        for (int nf = 0; nf < 2; nf++) {
            int row = row0 + m0w + mf * 16 + g;
            int col = n0w + nf * 8 + 2 * tg;
            float s0 = __ldg(scale + col), s1 = __ldg(scale + col + 1);
            float bb0 = __ldg(bias + col), bb1 = __ldg(bias + col + 1);
            if (row < N) {
                uint2 o;
                o.x = packf(fmaxf(fmaf(C[mf][nf][0], s0, bb0), 0.f));
                o.y = packf(fmaxf(fmaf(C[mf][nf][1], s1, bb1), 0.f));
                *(uint2*)(g_mid1p + (size_t)row * 64 + col) = o;
            }
            if (row + 8 < N) {
                uint2 o;
                o.x = packf(fmaxf(fmaf(C[mf][nf][2], s0, bb0), 0.f));
                o.y = packf(fmaxf(fmaf(C[mf][nf][3], s1, bb1), 0.f));
                *(uint2*)(g_mid1p + (size_t)(row + 8) * 64 + col) = o;
            }
        }
        __syncthreads();
    }
}

// ===========================================================================
// conv2: mid2p = split(relu((sum_ko gather(mid1,nbr[:,ko]) @ w2[ko])*s2+b2))
// smem: B 9x[64][72] u32 (165.9KB) + A[128][72] u32 (36.9KB) = 202,752 B
// ===========================================================================
__global__ void __launch_bounds__(512) conv2_k(
    const int* __restrict__ nbr, const float* __restrict__ scale,
    const float* __restrict__ bias, int N, int tiles)
{
    extern __shared__ uint32_t sm[];
    uint32_t* Bsm = sm;                    // [ko][64][72]
    uint32_t* Asm = sm + 9 * 64 * 72;      // [128][72]
    const int tid = threadIdx.x, w = tid >> 5, lane = tid & 31;
    const int g = lane >> 2, tg = lane & 3;
    const int m0w = (w & 3) * 32, n0w = (w >> 2) * 16;
    const int sr = tid >> 2, sq = tid & 3;

    for (int e = tid; e < 9216; e += 512) {   // 9*64 rows x 16 uint4
        uint4 v = ((const uint4*)g_w2p)[e];
        int ko = e >> 10, r = e & 1023, n = r >> 4, kq = r & 15;
        *(uint4*)(Bsm + ko * 4608 + n * 72 + kq * 4) = v;
    }
    __syncthreads();

    for (int t = blockIdx.x; t < tiles; t += gridDim.x) {
        const int row0 = t << 7;
        const int grow = row0 + sr;
        float C[2][2][4] = {};

        for (int ko = 0; ko < 9; ko++) {
            int nidx = (grow < N) ? nbr[grow * 9 + ko] : N;
            const uint4* src = (const uint4*)(g_mid1p + (size_t)nidx * 64);
            #pragma unroll
            for (int j = 0; j < 4; j++) {
                uint4 v = (nidx < N) ? src[sq * 4 + j] : make_uint4(0u, 0u, 0u, 0u);
                *(uint4*)(Asm + sr * 72 + sq * 16 + j * 4) = v;
            }
            __syncthreads();

            const uint32_t* Bko = Bsm + ko * 4608;
            #pragma unroll
            for (int s = 0; s < 4; s++) {
                int k0 = s * 16;
                AFrag a0 = load_a(Asm, 72, m0w, k0, g, tg);
                AFrag a1 = load_a(Asm, 72, m0w + 16, k0, g, tg);
                BFrag b0 = load_b(Bko, 72, n0w, k0, g, tg);
                BFrag b1 = load_b(Bko, 72, n0w + 8, k0, g, tg);
                mma3(C[0][0], a0, b0); mma3(C[0][1], a0, b1);
                mma3(C[1][0], a1, b0); mma3(C[1][1], a1, b1);
            }
            __syncthreads();
        }
        #pragma unroll
        for (int mf = 0; mf < 2; mf++)
        #pragma unroll
        for (int nf = 0; nf < 2; nf++) {
            int row = row0 + m0w + mf * 16 + g;
            int col = n0w + nf * 8 + 2 * tg;
            float s0 = __ldg(scale + col), s1 = __ldg(scale + col + 1);
            float bb0 = __ldg(bias + col), bb1 = __ldg(bias + col + 1);
            if (row < N) {
                uint2 o;
                o.x = packf(fmaxf(fmaf(C[mf][nf][0], s0, bb0), 0.f));
                o.y = packf(fmaxf(fmaf(C[mf][nf][1], s1, bb1), 0.f));
                *(uint2*)(g_mid2p + (size_t)row * 64 + col) = o;
            }
            if (row + 8 < N) {
                uint2 o;
                o.x = packf(fmaxf(fmaf(C[mf][nf][2], s0, bb0), 0.f));
                o.y = packf(fmaxf(fmaf(C[mf][nf][3], s1, bb1), 0.f));
                *(uint2*)(g_mid2p + (size_t)(row + 8) * 64 + col) = o;
            }
        }
    }
}

// ===========================================================================
// conv3: out = relu((mid2 @ w3)*s3 + b3 + feat)   M128 tile, K=64, N=256
// smem: A[128][72] (36.9KB) + B[256][72] (73.7KB) = 110,592 B
// 512 thr, 16 warps, warp-tile M32xN64
// ===========================================================================
__global__ void __launch_bounds__(512) conv3_k(
    const float* __restrict__ feat, const float* __restrict__ scale,
    const float* __restrict__ bias, float* __restrict__ out, int N, int tiles)
{
    extern __shared__ uint32_t sm[];
    uint32_t* Asm = sm;                 // [128][72]
    uint32_t* Bsm = sm + 128 * 72;      // [256][72]
    const int tid = threadIdx.x, w = tid >> 5, lane = tid & 31;
    const int g = lane >> 2, tg = lane & 3;
    const int m0w = (w & 3) * 32, n0w = (w >> 2) * 64;
    const int sr = tid >> 2, sq = tid & 3;

    for (int e = tid; e < 4096; e += 512) {   // 256 rows x 16 uint4
        uint4 v = ((const uint4*)g_w3p)[e];
        int n = e >> 4, kq = e & 15;
        *(uint4*)(Bsm + n * 72 + kq * 4) = v;
    }
    __syncthreads();

    for (int t = blockIdx.x; t < tiles; t += gridDim.x) {
        const int row0 = t << 7;
        const int grow = row0 + sr;
        const uint4* src = (const uint4*)(g_mid2p + (size_t)grow * 64);
        #pragma unroll
        for (int j = 0; j < 4; j++) {
            uint4 v = (grow < N) ? src[sq * 4 + j] : make_uint4(0u, 0u, 0u, 0u);
            *(uint4*)(Asm + sr * 72 + sq * 16 + j * 4) = v;
        }
        __syncthreads();

        float C[2][8][4] = {};
        #pragma unroll 2
        for (int s = 0; s < 4; s++) {
            int k0 = s * 16;
            AFrag a0 = load_a(Asm, 72, m0w, k0, g, tg);
            AFrag a1 = load_a(Asm, 72, m0w + 16, k0, g, tg);
            #pragma unroll
            for (int nf = 0; nf < 8; nf++) {
                BFrag b = load_b(Bsm, 72, n0w + nf * 8, k0, g, tg);
                mma3(C[0][nf], a0, b);
                mma3(C[1][nf], a1, b);
            }
        }
        #pragma unroll
        for (int mf = 0; mf < 2; mf++)
        #pragma unroll
        for (int nf = 0; nf < 8; nf++) {
            int row = row0 + m0w + mf * 16 + g;
            int col = n0w + nf * 8 + 2 * tg;
            float s0 = __ldg(scale + col), s1 = __ldg(scale + col + 1);
            float bb0 = __ldg(bias + col), bb1 = __ldg(bias + col + 1);
            if (row < N) {
                float2 f = *(const float2*)(feat + (size_t)row * 256 + col);
                float2 o;
                o.x = fmaxf(fmaf(C[mf][nf][0], s0, bb0) + f.x, 0.f);
                o.y = fmaxf(fmaf(C[mf][nf][1], s1, bb1) + f.y, 0.f);
                *(float2*)(out + (size_t)row * 256 + col) = o;
            }
            if (row + 8 < N) {
                float2 f = *(const float2*)(feat + (size_t)(row + 8) * 256 + col);
                float2 o;
                o.x = fmaxf(fmaf(C[mf][nf][2], s0, bb0) + f.x, 0.f);
                o.y = fmaxf(fmaf(C[mf][nf][3], s1, bb1) + f.y, 0.f);
                *(float2*)(out + (size_t)(row + 8) * 256 + col) = o;
            }
        }
        __syncthreads();
    }
}

// ---------------------------------------------------------------------------
extern "C" void kernel_launch(void* const* d_in, const int* in_sizes, int n_in,
                              void* d_out, int out_size)
{
    const float* feat = (const float*)d_in[0];
    const int*   nbr  = (const int*)  d_in[1];
    const float* w1   = (const float*)d_in[2];
    const float* s1   = (const float*)d_in[3];
    const float* b1   = (const float*)d_in[4];
    const float* w2   = (const float*)d_in[5];
    const float* s2   = (const float*)d_in[6];
    const float* b2   = (const float*)d_in[7];
    const float* w3   = (const float*)d_in[8];
    const float* s3   = (const float*)d_in[9];
    const float* b3   = (const float*)d_in[10];
    float* out = (float*)d_out;

    int N = in_sizes[0] / 256;
    if (N > MAX_N) N = MAX_N;
    int tiles = (N + 127) >> 7;

    const int sm1 = (128 * 264 + 64 * 264) * 4;    // 202752
    const int sm2 = (9 * 64 * 72 + 128 * 72) * 4;  // 202752
    const int sm3 = (128 * 72 + 256 * 72) * 4;     // 110592

    cudaFuncSetAttribute(conv1_k, cudaFuncAttributeMaxDynamicSharedMemorySize, sm1);
    cudaFuncSetAttribute(conv2_k, cudaFuncAttributeMaxDynamicSharedMemorySize, sm2);
    cudaFuncSetAttribute(conv3_k, cudaFuncAttributeMaxDynamicSharedMemorySize, sm3);

    prep_weights<<<64, 256>>>(w1, w2, w3);
    conv1_k<<<148, 512, sm1>>>(feat, s1, b1, N, tiles);
    conv2_k<<<148, 512, sm2>>>(nbr, s2, b2, N, tiles);
    conv3_k<<<148, 512, sm3>>>(feat, s3, b3, out, N, tiles);
}